// round 5
// baseline (speedup 1.0000x reference)
#include <cuda_runtime.h>
#include <cuda_bf16.h>
#include <math.h>
#include <stdio.h>

#define B_  4
#define S_  2048
#define D_  1024
#define H_  16
#define DK_ 64
#define NTOK (B_ * S_)          // 8192
#define SBH  (B_ * H_)          // 64

// ---------------- scratch (static device globals; no allocs) ----------------
__device__ float g_Q[(size_t)NTOK * D_];
__device__ float g_K[(size_t)NTOK * D_];
__device__ float g_V[(size_t)NTOK * D_];
__device__ float g_A[(size_t)NTOK * D_];
__device__ float g_S[(size_t)SBH * S_ * S_];   // score scratch
__device__ float g_cos[S_ * 32];
__device__ float g_sin[S_ * 32];

__device__ __forceinline__ float* dev_sel(int s) {
    switch (s) {
        case 0: return g_Q;
        case 1: return g_K;
        case 2: return g_V;
        case 3: return g_A;
    }
    return nullptr;
}

// ---------------- SGEMM: C[m][n] = sum_k A[m][k] * W[n][k] ------------------
#define GBM 128
#define GBN 128
#define GBK 16

__global__ __launch_bounds__(256) void gemm_nt(const float* Ap,
                                               const float* __restrict__ W,
                                               float* Cp,
                                               int asel, int csel,
                                               int M, int N, int K) {
    const float* A = (asel >= 0) ? dev_sel(asel) : Ap;
    float* C = (csel >= 0) ? dev_sel(csel) : Cp;

    __shared__ float As[GBK][GBM + 4];
    __shared__ float Bs[GBK][GBN + 4];

    const int bm = blockIdx.y * GBM;
    const int bn = blockIdx.x * GBN;
    const int tid = threadIdx.x;
    const int tx = tid & 15;
    const int ty = tid >> 4;

    const int lrow = tid >> 2;        // 0..63
    const int lk4  = (tid & 3) << 2;  // 0,4,8,12

    float acc[8][8];
#pragma unroll
    for (int i = 0; i < 8; ++i)
#pragma unroll
        for (int j = 0; j < 8; ++j) acc[i][j] = 0.f;

    for (int k0 = 0; k0 < K; k0 += GBK) {
#pragma unroll
        for (int r = 0; r < 2; ++r) {
            int row = lrow + r * 64;
            float4 v = *(const float4*)&A[(size_t)(bm + row) * K + k0 + lk4];
            As[lk4 + 0][row] = v.x;
            As[lk4 + 1][row] = v.y;
            As[lk4 + 2][row] = v.z;
            As[lk4 + 3][row] = v.w;
        }
#pragma unroll
        for (int r = 0; r < 2; ++r) {
            int row = lrow + r * 64;
            float4 v = *(const float4*)&W[(size_t)(bn + row) * K + k0 + lk4];
            Bs[lk4 + 0][row] = v.x;
            Bs[lk4 + 1][row] = v.y;
            Bs[lk4 + 2][row] = v.z;
            Bs[lk4 + 3][row] = v.w;
        }
        __syncthreads();

#pragma unroll
        for (int k = 0; k < GBK; ++k) {
            float a[8], b[8];
            *(float4*)&a[0] = *(const float4*)&As[k][ty * 8];
            *(float4*)&a[4] = *(const float4*)&As[k][ty * 8 + 4];
            *(float4*)&b[0] = *(const float4*)&Bs[k][tx * 8];
            *(float4*)&b[4] = *(const float4*)&Bs[k][tx * 8 + 4];
#pragma unroll
            for (int i = 0; i < 8; ++i)
#pragma unroll
                for (int j = 0; j < 8; ++j) acc[i][j] += a[i] * b[j];
        }
        __syncthreads();
    }

#pragma unroll
    for (int i = 0; i < 8; ++i) {
        int row = bm + ty * 8 + i;
#pragma unroll
        for (int j = 0; j < 8; j += 4) {
            *(float4*)&C[(size_t)row * N + bn + tx * 8 + j] =
                make_float4(acc[i][j], acc[i][j + 1], acc[i][j + 2], acc[i][j + 3]);
        }
    }
}

// ---------------- RoPE trig table: ang[s][i] = pos[s] * 10000^(-i/32) -------
__global__ __launch_bounds__(256) void build_trig(const int* __restrict__ pos) {
    int idx = blockIdx.x * blockDim.x + threadIdx.x;
    if (idx >= S_ * 32) return;
    int s = idx >> 5;
    int i = idx & 31;
    double inv = pow(10000.0, -(double)(2 * i) / 64.0);
    double ang = (double)pos[s] * inv;
    g_cos[idx] = (float)cos(ang);
    g_sin[idx] = (float)sin(ang);
}

// ---------------- RoPE apply (in-place on g_Q, g_K; NO scaling here) --------
__global__ __launch_bounds__(256) void rope_apply() {
    int idx = blockIdx.x * blockDim.x + threadIdx.x;
    if (idx >= NTOK * (D_ / 2)) return;

    int i   = idx & 31;         // pair index within head
    int r   = idx >> 5;         // tok*H + h
    int h   = r & 15;
    int tok = r >> 4;
    int s   = tok & (S_ - 1);

    float c  = g_cos[(s << 5) + i];
    float sn = g_sin[(s << 5) + i];

    size_t base = (size_t)tok * D_ + (size_t)h * DK_ + 2 * i;

    float2 q = *(float2*)&g_Q[base];
    *(float2*)&g_Q[base] = make_float2(q.x * c - q.y * sn, q.x * sn + q.y * c);

    float2 k = *(float2*)&g_K[base];
    *(float2*)&g_K[base] = make_float2(k.x * c - k.y * sn, k.x * sn + k.y * c);
}

// ---------------- scores: S[q][k] = (Q[q]·K[k]) / 8, causal tiles only ------
__global__ __launch_bounds__(256) void attn_scores() {
    const int kt = blockIdx.x;
    const int qt = blockIdx.y;
    if (kt > qt) return;
    const int bh = blockIdx.z;
    const int b = bh >> 4, h = bh & 15;
    const size_t base = (size_t)b * S_ * D_ + (size_t)h * DK_;

    __shared__ float Qs[64][65];
    __shared__ float Ks[64][65];

    const int tid = threadIdx.x;
    const int tx = tid & 15;
    const int ty = tid >> 4;

#pragma unroll
    for (int p = 0; p < 4; ++p) {
        int idx = tid + p * 256;
        int row = idx >> 4;
        int c4  = (idx & 15) << 2;
        float4 v = *(const float4*)(g_Q + base + (size_t)(qt * 64 + row) * D_ + c4);
        Qs[row][c4 + 0] = v.x; Qs[row][c4 + 1] = v.y;
        Qs[row][c4 + 2] = v.z; Qs[row][c4 + 3] = v.w;
        float4 w = *(const float4*)(g_K + base + (size_t)(kt * 64 + row) * D_ + c4);
        Ks[row][c4 + 0] = w.x; Ks[row][c4 + 1] = w.y;
        Ks[row][c4 + 2] = w.z; Ks[row][c4 + 3] = w.w;
    }
    __syncthreads();

    float acc[4][4];
#pragma unroll
    for (int i = 0; i < 4; ++i)
#pragma unroll
        for (int j = 0; j < 4; ++j) acc[i][j] = 0.f;

#pragma unroll 8
    for (int d = 0; d < 64; ++d) {
        float qa[4], ka[4];
#pragma unroll
        for (int i = 0; i < 4; ++i) qa[i] = Qs[ty * 4 + i][d];
#pragma unroll
        for (int j = 0; j < 4; ++j) ka[j] = Ks[tx * 4 + j][d];
#pragma unroll
        for (int i = 0; i < 4; ++i)
#pragma unroll
            for (int j = 0; j < 4; ++j) acc[i][j] += qa[i] * ka[j];
    }

    float* Sp = g_S + (size_t)bh * S_ * S_;
#pragma unroll
    for (int i = 0; i < 4; ++i) {
        size_t off = (size_t)(qt * 64 + ty * 4 + i) * S_ + kt * 64 + tx * 4;
        *(float4*)(Sp + off) = make_float4(acc[i][0] * 0.125f, acc[i][1] * 0.125f,
                                           acc[i][2] * 0.125f, acc[i][3] * 0.125f);
    }
}

// ---------------- softmax per row (reads only k<=q; zero-fills to tile end) -
__global__ __launch_bounds__(256) void attn_softmax() {
    const int q  = blockIdx.x;
    const int bh = blockIdx.y;
    float* row = g_S + (size_t)bh * S_ * S_ + (size_t)q * S_;
    const int L = q + 1;
    const int tid = threadIdx.x;

    __shared__ float red[256];

    float mx = -1e30f;
    for (int k = tid; k < L; k += 256) mx = fmaxf(mx, row[k]);
    red[tid] = mx;
    __syncthreads();
    for (int s = 128; s; s >>= 1) {
        if (tid < s) red[tid] = fmaxf(red[tid], red[tid + s]);
        __syncthreads();
    }
    mx = red[0];
    __syncthreads();

    float sum = 0.f;
    for (int k = tid; k < L; k += 256) {
        float e = __expf(row[k] - mx);
        row[k] = e;
        sum += e;
    }
    red[tid] = sum;
    __syncthreads();
    for (int s = 128; s; s >>= 1) {
        if (tid < s) red[tid] += red[tid + s];
        __syncthreads();
    }
    float inv = 1.f / red[0];

    for (int k = tid; k < L; k += 256) row[k] *= inv;

    const int tend = ((q >> 6) + 1) << 6;   // end of diagonal 64-tile
    for (int k = L + tid; k < tend; k += 256) row[k] = 0.f;
}

// ---------------- PV: A[q][e] = sum_k P[q][k] * V[k][e] ---------------------
__global__ __launch_bounds__(256) void attn_pv() {
    const int qt = blockIdx.x;
    const int bh = blockIdx.y;
    const int b = bh >> 4, h = bh & 15;
    const size_t base = (size_t)b * S_ * D_ + (size_t)h * DK_;
    const float* Sp = g_S + (size_t)bh * S_ * S_;

    __shared__ float Ps[64][65];
    __shared__ float Vs[64][65];

    const int tid = threadIdx.x;
    const int tx = tid & 15;
    const int ty = tid >> 4;

    float acc[4][4];
#pragma unroll
    for (int i = 0; i < 4; ++i)
#pragma unroll
        for (int j = 0; j < 4; ++j) acc[i][j] = 0.f;

    for (int kt = 0; kt <= qt; ++kt) {
        __syncthreads();
#pragma unroll
        for (int p = 0; p < 4; ++p) {
            int idx = tid + p * 256;
            int row = idx >> 4;
            int c4  = (idx & 15) << 2;
            float4 v = *(const float4*)(Sp + (size_t)(qt * 64 + row) * S_ + kt * 64 + c4);
            Ps[row][c4 + 0] = v.x; Ps[row][c4 + 1] = v.y;
            Ps[row][c4 + 2] = v.z; Ps[row][c4 + 3] = v.w;
            float4 w = *(const float4*)(g_V + base + (size_t)(kt * 64 + row) * D_ + c4);
            Vs[row][c4 + 0] = w.x; Vs[row][c4 + 1] = w.y;
            Vs[row][c4 + 2] = w.z; Vs[row][c4 + 3] = w.w;
        }
        __syncthreads();

#pragma unroll 8
        for (int kk = 0; kk < 64; ++kk) {
            float pa[4], va[4];
#pragma unroll
            for (int i = 0; i < 4; ++i) pa[i] = Ps[ty * 4 + i][kk];
#pragma unroll
            for (int j = 0; j < 4; ++j) va[j] = Vs[kk][tx * 4 + j];
#pragma unroll
            for (int i = 0; i < 4; ++i)
#pragma unroll
                for (int j = 0; j < 4; ++j) acc[i][j] += pa[i] * va[j];
        }
    }

#pragma unroll
    for (int i = 0; i < 4; ++i) {
        *(float4*)(g_A + base + (size_t)(qt * 64 + ty * 4 + i) * D_ + tx * 4) =
            make_float4(acc[i][0], acc[i][1], acc[i][2], acc[i][3]);
    }
}

// ---------------- debug stats (1 thread; prints stage health) ---------------
__global__ void dbg_kernel(const float* x, const int* pos, const float* Wq,
                           const float* out) {
    if (blockIdx.x || threadIdx.x) return;
    double aq = 0, ak = 0, av = 0, aa = 0, ao = 0;
    const size_t N = (size_t)NTOK * D_;
    for (int t = 0; t < 4096; ++t) {
        size_t j = ((size_t)t * 2053 + 7) % N;
        aq += fabsf(g_Q[j]); ak += fabsf(g_K[j]); av += fabsf(g_V[j]);
        aa += fabsf(g_A[j]); ao += fabsf(out[j]);
    }
    const float* row = g_S + (size_t)1000 * S_;   // bh=0, q=1000
    float mx = 0.f; double sm = 0.0;
    for (int k = 0; k <= 1000; ++k) { mx = fmaxf(mx, row[k]); sm += row[k]; }
    printf("DBG pos[0,1,2047]=%d,%d,%d x0=%.5f Wq0=%.5f cos(1)=%.5f sin31=%.6f\n",
           pos[0], pos[1], pos[2047], x[0], Wq[0], g_cos[32], g_sin[32 + 31]);
    printf("DBG m|Q|=%.4f m|K|=%.4f m|V|=%.4f m|A|=%.4f m|out|=%.4f "
           "P1000 max=%.5f sum=%.5f\n",
           aq / 4096, ak / 4096, av / 4096, aa / 4096, ao / 4096, mx, (float)sm);
}

// ---------------- launch -----------------------------------------------------
extern "C" void kernel_launch(void* const* d_in, const int* in_sizes, int n_in,
                              void* d_out, int out_size) {
    fprintf(stderr, "KLDBG n_in=%d sizes:", n_in);
    for (int i = 0; i < n_in; ++i) fprintf(stderr, " [%d]=%d", i, in_sizes[i]);
    fprintf(stderr, " out=%d\n", out_size);

    // Identify x and pos by size; weights keep relative metadata order.
    int ix = 0, ipos = 1;
    int iw[4] = {2, 3, 4, 5};
    {
        int nw = 0, found_x = 0, found_p = 0, tmp[8];
        for (int i = 0; i < n_in && i < 8; ++i) {
            if (in_sizes[i] == S_) { ipos = i; found_p = 1; }
            else if (in_sizes[i] == NTOK * D_) { ix = i; found_x = 1; }
            else if (nw < 8) tmp[nw++] = i;
        }
        if (found_x && found_p && nw >= 4) {
            iw[0] = tmp[0]; iw[1] = tmp[1]; iw[2] = tmp[2]; iw[3] = tmp[3];
        }
    }

    const float* x  = (const float*)d_in[ix];
    const int* pos  = (const int*)d_in[ipos];
    const float* Wq = (const float*)d_in[iw[0]];
    const float* Wk = (const float*)d_in[iw[1]];
    const float* Wv = (const float*)d_in[iw[2]];
    const float* Wo = (const float*)d_in[iw[3]];
    float* out = (float*)d_out;

    dim3 gg(D_ / GBN, NTOK / GBM);  // (8, 64)
    gemm_nt<<<gg, 256>>>(x, Wq, nullptr, -1, 0, NTOK, D_, D_);  // -> g_Q
    gemm_nt<<<gg, 256>>>(x, Wk, nullptr, -1, 1, NTOK, D_, D_);  // -> g_K
    gemm_nt<<<gg, 256>>>(x, Wv, nullptr, -1, 2, NTOK, D_, D_);  // -> g_V

    build_trig<<<(S_ * 32 + 255) / 256, 256>>>(pos);

    int rope_total = NTOK * (D_ / 2);
    rope_apply<<<(rope_total + 255) / 256, 256>>>();

    dim3 sg(S_ / 64, S_ / 64, SBH);   // (32, 32, 64)
    attn_scores<<<sg, 256>>>();

    dim3 smg(S_, SBH);                // (2048, 64)
    attn_softmax<<<smg, 256>>>();

    dim3 pvg(S_ / 64, SBH);           // (32, 64)
    attn_pv<<<pvg, 256>>>();

    gemm_nt<<<gg, 256>>>(nullptr, Wo, out, 3, -1, NTOK, D_, D_);  // g_A -> out

    dbg_kernel<<<1, 32>>>(x, pos, Wq, out);
}

// round 9
// speedup vs baseline: 2.0567x; 2.0567x over previous
#include <cuda_runtime.h>
#include <cuda_bf16.h>
#include <math.h>
#include <cstdint>

#define B_  4
#define S_  2048
#define D_  1024
#define H_  16
#define DK_ 64
#define NTOK (B_ * S_)          // 8192
#define SBH  (B_ * H_)          // 64

// ---------------- scratch (static device globals; no allocs) ----------------
__device__ float g_Q[(size_t)NTOK * D_];
__device__ float g_K[(size_t)NTOK * D_];
__device__ float g_V[(size_t)NTOK * D_];
__device__ float g_A[(size_t)NTOK * D_];
__device__ float g_S[(size_t)SBH * S_ * S_];   // score scratch
__device__ float g_cos[S_ * 32];
__device__ float g_sin[S_ * 32];
__device__ __nv_bfloat16 g_xhi[(size_t)NTOK * D_];
__device__ __nv_bfloat16 g_xlo[(size_t)NTOK * D_];
__device__ __nv_bfloat16 g_Ahi[(size_t)NTOK * D_];
__device__ __nv_bfloat16 g_Alo[(size_t)NTOK * D_];
__device__ __nv_bfloat16 g_Whi[4 * 1024 * 1024];
__device__ __nv_bfloat16 g_Wlo[4 * 1024 * 1024];

// ---------------- warp-level MMA helpers (sm_80 baseline; no 'a' needed) ----
__device__ __forceinline__ void ldsm4(uint32_t* r, uint32_t addr) {
    asm volatile(
        "ldmatrix.sync.aligned.m8n8.x4.shared.b16 {%0,%1,%2,%3}, [%4];"
        : "=r"(r[0]), "=r"(r[1]), "=r"(r[2]), "=r"(r[3]) : "r"(addr));
}
__device__ __forceinline__ void mma16816(float* c, const uint32_t* a,
                                         const uint32_t* b) {
    asm volatile(
        "mma.sync.aligned.m16n8k16.row.col.f32.bf16.bf16.f32 "
        "{%0,%1,%2,%3}, {%4,%5,%6,%7}, {%8,%9}, {%0,%1,%2,%3};"
        : "+f"(c[0]), "+f"(c[1]), "+f"(c[2]), "+f"(c[3])
        : "r"(a[0]), "r"(a[1]), "r"(a[2]), "r"(a[3]), "r"(b[0]), "r"(b[1]));
}
__device__ __forceinline__ uint32_t smem_u32(const void* p) {
    uint32_t a;
    asm("{ .reg .u64 t; cvta.to.shared.u64 t, %1; cvt.u32.u64 %0, t; }"
        : "=r"(a) : "l"(p));
    return a;
}

// ---------------- split fp32 -> (hi, lo) bf16 --------------------------------
// dsel: 0=x, 1..4=W[dsel-1], 5=A. ssel: 0=use src param, 1=read g_A.
__global__ __launch_bounds__(256) void split_k(const float* src, int ssel,
                                               int dsel, int n4) {
    int i = blockIdx.x * 256 + threadIdx.x;
    if (i >= n4) return;
    const float* s = (ssel == 0) ? src : g_A;
    __nv_bfloat16 *hi, *lo;
    switch (dsel) {
        case 0: hi = g_xhi; lo = g_xlo; break;
        case 5: hi = g_Ahi; lo = g_Alo; break;
        default:
            hi = g_Whi + (size_t)(dsel - 1) * 1048576;
            lo = g_Wlo + (size_t)(dsel - 1) * 1048576;
    }
    float4 v = *(const float4*)(s + 4 * (size_t)i);
    float vv[4] = {v.x, v.y, v.z, v.w};
    __nv_bfloat16 h[4], l[4];
#pragma unroll
    for (int j = 0; j < 4; ++j) {
        h[j] = __float2bfloat16(vv[j]);
        l[j] = __float2bfloat16(vv[j] - __bfloat162float(h[j]));
    }
    *(uint2*)(hi + 4 * (size_t)i) = *(uint2*)h;
    *(uint2*)(lo + 4 * (size_t)i) = *(uint2*)l;
}

// ---------------- HMMA split-bf16 GEMM: C = A @ W^T -------------------------
// C[m][n] = sum_k (Ahi+Alo)[m][k]*(Whi+Wlo)[n][k]  (hi*hi + lo*hi + hi*lo)
// M=8192, N=1024, K=1024. 128x128 tile/CTA, BK=32, 8 warps (2m x 4n),
// per warp 64x32 = 4x4 tiles of m16n8k16. Smem row stride 40 bf16 (80 B).
#define GST 40   // smem row stride in bf16

__global__ __launch_bounds__(256) void gemm_mma(int asel, int wsel, int csel,
                                                float* Cout) {
    __shared__ __nv_bfloat16 sAh[128 * GST];
    __shared__ __nv_bfloat16 sAl[128 * GST];
    __shared__ __nv_bfloat16 sWh[128 * GST];
    __shared__ __nv_bfloat16 sWl[128 * GST];

    const int tid = threadIdx.x, wid = tid >> 5, lid = tid & 31;
    const int wr = wid & 1, wc = wid >> 1;       // 2 m-rows x 4 n-cols of warps
    const int m0 = blockIdx.y * 128, n0 = blockIdx.x * 128;

    const __nv_bfloat16* Ah = asel ? g_Ahi : g_xhi;
    const __nv_bfloat16* Al = asel ? g_Alo : g_xlo;
    const __nv_bfloat16* Wh = g_Whi + (size_t)wsel * 1048576;
    const __nv_bfloat16* Wl = g_Wlo + (size_t)wsel * 1048576;
    float* C;
    switch (csel) {
        case 0: C = g_Q; break;
        case 1: C = g_K; break;
        case 2: C = g_V; break;
        default: C = Cout;
    }

    const uint32_t bAh = smem_u32(sAh), bAl = smem_u32(sAl);
    const uint32_t bWh = smem_u32(sWh), bWl = smem_u32(sWl);

    // ldmatrix per-lane row/col selectors (bf16 units).
    const int rowSelA = wr * 64 + (lid & 15);          // + mt*16
    const int kSelA   = (lid >> 4) * 8;                // + ks*16
    const int rowSelW = wc * 32 + ((lid >> 4) * 8) + (lid & 7);  // + nt16*16
    const int kSelW   = ((lid >> 3) & 1) * 8;          // + ks*16

    float acc[4][4][4];
#pragma unroll
    for (int i = 0; i < 4; ++i)
#pragma unroll
        for (int j = 0; j < 4; ++j)
#pragma unroll
            for (int t = 0; t < 4; ++t) acc[i][j][t] = 0.f;

    for (int k0 = 0; k0 < 1024; k0 += 32) {
        __syncthreads();
        // Load 4 tiles of 128x32 bf16 (512 uint4 chunks each).
#pragma unroll
        for (int p = 0; p < 2; ++p) {
            int c = tid + p * 256;
            int row = c >> 2, kc = (c & 3) * 8;
            int so = row * GST + kc;
            size_t ao = (size_t)(m0 + row) * 1024 + k0 + kc;
            size_t wo = (size_t)(n0 + row) * 1024 + k0 + kc;
            *(uint4*)(sAh + so) = *(const uint4*)(Ah + ao);
            *(uint4*)(sAl + so) = *(const uint4*)(Al + ao);
            *(uint4*)(sWh + so) = *(const uint4*)(Wh + wo);
            *(uint4*)(sWl + so) = *(const uint4*)(Wl + wo);
        }
        __syncthreads();

#pragma unroll
        for (int ks = 0; ks < 2; ++ks) {
            uint32_t bh[4][2], bl[4][2];
#pragma unroll
            for (int nt16 = 0; nt16 < 2; ++nt16) {
                uint32_t r[4];
                uint32_t off =
                    (uint32_t)((rowSelW + nt16 * 16) * GST + ks * 16 + kSelW) * 2;
                ldsm4(r, bWh + off);
                bh[nt16 * 2][0] = r[0]; bh[nt16 * 2][1] = r[1];
                bh[nt16 * 2 + 1][0] = r[2]; bh[nt16 * 2 + 1][1] = r[3];
                ldsm4(r, bWl + off);
                bl[nt16 * 2][0] = r[0]; bl[nt16 * 2][1] = r[1];
                bl[nt16 * 2 + 1][0] = r[2]; bl[nt16 * 2 + 1][1] = r[3];
            }
            uint32_t a[4][4];
#pragma unroll
            for (int mt = 0; mt < 4; ++mt)
                ldsm4(a[mt],
                      bAh + (uint32_t)((rowSelA + mt * 16) * GST + ks * 16 + kSelA) * 2);
#pragma unroll
            for (int mt = 0; mt < 4; ++mt)
#pragma unroll
                for (int nt = 0; nt < 4; ++nt) {
                    mma16816(acc[mt][nt], a[mt], bh[nt]);
                    mma16816(acc[mt][nt], a[mt], bl[nt]);
                }
#pragma unroll
            for (int mt = 0; mt < 4; ++mt)
                ldsm4(a[mt],
                      bAl + (uint32_t)((rowSelA + mt * 16) * GST + ks * 16 + kSelA) * 2);
#pragma unroll
            for (int mt = 0; mt < 4; ++mt)
#pragma unroll
                for (int nt = 0; nt < 4; ++nt)
                    mma16816(acc[mt][nt], a[mt], bh[nt]);
        }
    }

    // Epilogue: C frag -> global. c0,c1: row g, cols 2j,2j+1; c2,c3: row g+8.
    const int g = lid >> 2, j2 = (lid & 3) * 2;
#pragma unroll
    for (int mt = 0; mt < 4; ++mt) {
        int row = m0 + wr * 64 + mt * 16 + g;
#pragma unroll
        for (int nt = 0; nt < 4; ++nt) {
            int col = n0 + wc * 32 + nt * 8 + j2;
            *(float2*)&C[(size_t)row * 1024 + col] =
                make_float2(acc[mt][nt][0], acc[mt][nt][1]);
            *(float2*)&C[(size_t)(row + 8) * 1024 + col] =
                make_float2(acc[mt][nt][2], acc[mt][nt][3]);
        }
    }
}

// ---------------- RoPE trig table -------------------------------------------
__global__ __launch_bounds__(256) void build_trig(const int* __restrict__ pos) {
    int idx = blockIdx.x * blockDim.x + threadIdx.x;
    if (idx >= S_ * 32) return;
    int s = idx >> 5;
    int i = idx & 31;
    double inv = pow(10000.0, -(double)(2 * i) / 64.0);
    double ang = (double)pos[s] * inv;
    g_cos[idx] = (float)cos(ang);
    g_sin[idx] = (float)sin(ang);
}

// ---------------- RoPE apply (in-place on g_Q, g_K) -------------------------
__global__ __launch_bounds__(256) void rope_apply() {
    int idx = blockIdx.x * blockDim.x + threadIdx.x;
    if (idx >= NTOK * (D_ / 2)) return;
    int i   = idx & 31;
    int r   = idx >> 5;
    int h   = r & 15;
    int tok = r >> 4;
    int s   = tok & (S_ - 1);
    float c  = g_cos[(s << 5) + i];
    float sn = g_sin[(s << 5) + i];
    size_t base = (size_t)tok * D_ + (size_t)h * DK_ + 2 * i;
    float2 q = *(float2*)&g_Q[base];
    *(float2*)&g_Q[base] = make_float2(q.x * c - q.y * sn, q.x * sn + q.y * c);
    float2 k = *(float2*)&g_K[base];
    *(float2*)&g_K[base] = make_float2(k.x * c - k.y * sn, k.x * sn + k.y * c);
}

// ---------------- scores: S[q][k] = (Q[q]·K[k]) / 8, causal tiles only ------
__global__ __launch_bounds__(256) void attn_scores() {
    const int kt = blockIdx.x;
    const int qt = blockIdx.y;
    if (kt > qt) return;
    const int bh = blockIdx.z;
    const int b = bh >> 4, h = bh & 15;
    const size_t base = (size_t)b * S_ * D_ + (size_t)h * DK_;

    __shared__ float Qs[64][65];
    __shared__ float Ks[64][65];

    const int tid = threadIdx.x;
    const int tx = tid & 15;
    const int ty = tid >> 4;

#pragma unroll
    for (int p = 0; p < 4; ++p) {
        int idx = tid + p * 256;
        int row = idx >> 4;
        int c4  = (idx & 15) << 2;
        float4 v = *(const float4*)(g_Q + base + (size_t)(qt * 64 + row) * D_ + c4);
        Qs[row][c4 + 0] = v.x; Qs[row][c4 + 1] = v.y;
        Qs[row][c4 + 2] = v.z; Qs[row][c4 + 3] = v.w;
        float4 w = *(const float4*)(g_K + base + (size_t)(kt * 64 + row) * D_ + c4);
        Ks[row][c4 + 0] = w.x; Ks[row][c4 + 1] = w.y;
        Ks[row][c4 + 2] = w.z; Ks[row][c4 + 3] = w.w;
    }
    __syncthreads();

    float acc[4][4];
#pragma unroll
    for (int i = 0; i < 4; ++i)
#pragma unroll
        for (int j = 0; j < 4; ++j) acc[i][j] = 0.f;

#pragma unroll 8
    for (int d = 0; d < 64; ++d) {
        float qa[4], ka[4];
#pragma unroll
        for (int i = 0; i < 4; ++i) qa[i] = Qs[ty * 4 + i][d];
#pragma unroll
        for (int j = 0; j < 4; ++j) ka[j] = Ks[tx * 4 + j][d];
#pragma unroll
        for (int i = 0; i < 4; ++i)
#pragma unroll
            for (int j = 0; j < 4; ++j) acc[i][j] += qa[i] * ka[j];
    }

    float* Sp = g_S + (size_t)bh * S_ * S_;
#pragma unroll
    for (int i = 0; i < 4; ++i) {
        size_t off = (size_t)(qt * 64 + ty * 4 + i) * S_ + kt * 64 + tx * 4;
        *(float4*)(Sp + off) = make_float4(acc[i][0] * 0.125f, acc[i][1] * 0.125f,
                                           acc[i][2] * 0.125f, acc[i][3] * 0.125f);
    }
}

// ---------------- softmax per row -------------------------------------------
__global__ __launch_bounds__(256) void attn_softmax() {
    const int q  = blockIdx.x;
    const int bh = blockIdx.y;
    float* row = g_S + (size_t)bh * S_ * S_ + (size_t)q * S_;
    const int L = q + 1;
    const int tid = threadIdx.x;

    __shared__ float red[256];

    float mx = -1e30f;
    for (int k = tid; k < L; k += 256) mx = fmaxf(mx, row[k]);
    red[tid] = mx;
    __syncthreads();
    for (int s = 128; s; s >>= 1) {
        if (tid < s) red[tid] = fmaxf(red[tid], red[tid + s]);
        __syncthreads();
    }
    mx = red[0];
    __syncthreads();

    float sum = 0.f;
    for (int k = tid; k < L; k += 256) {
        float e = __expf(row[k] - mx);
        row[k] = e;
        sum += e;
    }
    red[tid] = sum;
    __syncthreads();
    for (int s = 128; s; s >>= 1) {
        if (tid < s) red[tid] += red[tid + s];
        __syncthreads();
    }
    float inv = 1.f / red[0];

    for (int k = tid; k < L; k += 256) row[k] *= inv;

    const int tend = ((q >> 6) + 1) << 6;
    for (int k = L + tid; k < tend; k += 256) row[k] = 0.f;
}

// ---------------- PV: A[q][e] = sum_k P[q][k] * V[k][e] ---------------------
__global__ __launch_bounds__(256) void attn_pv() {
    const int qt = blockIdx.x;
    const int bh = blockIdx.y;
    const int b = bh >> 4, h = bh & 15;
    const size_t base = (size_t)b * S_ * D_ + (size_t)h * DK_;
    const float* Sp = g_S + (size_t)bh * S_ * S_;

    __shared__ float Ps[64][65];
    __shared__ float Vs[64][65];

    const int tid = threadIdx.x;
    const int tx = tid & 15;
    const int ty = tid >> 4;

    float acc[4][4];
#pragma unroll
    for (int i = 0; i < 4; ++i)
#pragma unroll
        for (int j = 0; j < 4; ++j) acc[i][j] = 0.f;

    for (int kt = 0; kt <= qt; ++kt) {
        __syncthreads();
#pragma unroll
        for (int p = 0; p < 4; ++p) {
            int idx = tid + p * 256;
            int row = idx >> 4;
            int c4  = (idx & 15) << 2;
            float4 v = *(const float4*)(Sp + (size_t)(qt * 64 + row) * S_ + kt * 64 + c4);
            Ps[row][c4 + 0] = v.x; Ps[row][c4 + 1] = v.y;
            Ps[row][c4 + 2] = v.z; Ps[row][c4 + 3] = v.w;
            float4 w = *(const float4*)(g_V + base + (size_t)(kt * 64 + row) * D_ + c4);
            Vs[row][c4 + 0] = w.x; Vs[row][c4 + 1] = w.y;
            Vs[row][c4 + 2] = w.z; Vs[row][c4 + 3] = w.w;
        }
        __syncthreads();

#pragma unroll 8
        for (int kk = 0; kk < 64; ++kk) {
            float pa[4], va[4];
#pragma unroll
            for (int i = 0; i < 4; ++i) pa[i] = Ps[ty * 4 + i][kk];
#pragma unroll
            for (int j = 0; j < 4; ++j) va[j] = Vs[kk][tx * 4 + j];
#pragma unroll
            for (int i = 0; i < 4; ++i)
#pragma unroll
                for (int j = 0; j < 4; ++j) acc[i][j] += pa[i] * va[j];
        }
    }

#pragma unroll
    for (int i = 0; i < 4; ++i) {
        *(float4*)(g_A + base + (size_t)(qt * 64 + ty * 4 + i) * D_ + tx * 4) =
            make_float4(acc[i][0], acc[i][1], acc[i][2], acc[i][3]);
    }
}

// ---------------- launch -----------------------------------------------------
extern "C" void kernel_launch(void* const* d_in, const int* in_sizes, int n_in,
                              void* d_out, int out_size) {
    // Identify x and pos by size; weights keep relative metadata order.
    int ix = 0, ipos = 1;
    int iw[4] = {2, 3, 4, 5};
    {
        int nw = 0, found_x = 0, found_p = 0, tmp[8];
        for (int i = 0; i < n_in && i < 8; ++i) {
            if (in_sizes[i] == S_) { ipos = i; found_p = 1; }
            else if (in_sizes[i] == NTOK * D_) { ix = i; found_x = 1; }
            else if (nw < 8) tmp[nw++] = i;
        }
        if (found_x && found_p && nw >= 4) {
            iw[0] = tmp[0]; iw[1] = tmp[1]; iw[2] = tmp[2]; iw[3] = tmp[3];
        }
    }

    const float* x  = (const float*)d_in[ix];
    const int* pos  = (const int*)d_in[ipos];
    const float* Wq = (const float*)d_in[iw[0]];
    const float* Wk = (const float*)d_in[iw[1]];
    const float* Wv = (const float*)d_in[iw[2]];
    const float* Wo = (const float*)d_in[iw[3]];
    float* out = (float*)d_out;

    // Splits: x and the 4 weights.
    split_k<<<(NTOK * D_ / 4 + 255) / 256, 256>>>(x, 0, 0, NTOK * D_ / 4);
    split_k<<<(1048576 / 4 + 255) / 256, 256>>>(Wq, 0, 1, 1048576 / 4);
    split_k<<<(1048576 / 4 + 255) / 256, 256>>>(Wk, 0, 2, 1048576 / 4);
    split_k<<<(1048576 / 4 + 255) / 256, 256>>>(Wv, 0, 3, 1048576 / 4);
    split_k<<<(1048576 / 4 + 255) / 256, 256>>>(Wo, 0, 4, 1048576 / 4);

    // Projections on tensor cores (HMMA mma.sync).
    dim3 gg(D_ / 128, NTOK / 128);  // (8, 64)
    gemm_mma<<<gg, 256>>>(0, 0, 0, nullptr);  // x @ Wq^T -> g_Q
    gemm_mma<<<gg, 256>>>(0, 1, 1, nullptr);  // x @ Wk^T -> g_K
    gemm_mma<<<gg, 256>>>(0, 2, 2, nullptr);  // x @ Wv^T -> g_V

    build_trig<<<(S_ * 32 + 255) / 256, 256>>>(pos);
    int rope_total = NTOK * (D_ / 2);
    rope_apply<<<(rope_total + 255) / 256, 256>>>();

    dim3 sg(S_ / 64, S_ / 64, SBH);
    attn_scores<<<sg, 256>>>();

    dim3 smg(S_, SBH);
    attn_softmax<<<smg, 256>>>();

    dim3 pvg(S_ / 64, SBH);
    attn_pv<<<pvg, 256>>>();

    // Output projection on tensor cores.
    split_k<<<(NTOK * D_ / 4 + 255) / 256, 256>>>(nullptr, 1, 5, NTOK * D_ / 4);
    gemm_mma<<<gg, 256>>>(1, 3, 3, out);      // A @ Wo^T -> out
}

// round 10
// speedup vs baseline: 5.0262x; 2.4438x over previous
#include <cuda_runtime.h>
#include <cuda_bf16.h>
#include <math.h>
#include <cstdint>

#define B_  4
#define S_  2048
#define D_  1024
#define H_  16
#define DK_ 64
#define NTOK (B_ * S_)          // 8192
#define SBH  (B_ * H_)          // 64

// ---------------- scratch (static device globals; no allocs) ----------------
__device__ float g_Q[(size_t)NTOK * D_];
__device__ float g_K[(size_t)NTOK * D_];
__device__ float g_V[(size_t)NTOK * D_];
__device__ float g_A[(size_t)NTOK * D_];
__device__ float g_cos[S_ * 32];
__device__ float g_sin[S_ * 32];
__device__ __nv_bfloat16 g_xhi[(size_t)NTOK * D_];
__device__ __nv_bfloat16 g_xlo[(size_t)NTOK * D_];
__device__ __nv_bfloat16 g_Ahi[(size_t)NTOK * D_];
__device__ __nv_bfloat16 g_Alo[(size_t)NTOK * D_];
__device__ __nv_bfloat16 g_Whi[4 * 1024 * 1024];
__device__ __nv_bfloat16 g_Wlo[4 * 1024 * 1024];
__device__ __nv_bfloat16 g_Qh[(size_t)NTOK * D_];
__device__ __nv_bfloat16 g_Ql[(size_t)NTOK * D_];
__device__ __nv_bfloat16 g_Kh[(size_t)NTOK * D_];
__device__ __nv_bfloat16 g_Kl[(size_t)NTOK * D_];
__device__ __nv_bfloat16 g_Vh[(size_t)NTOK * D_];
__device__ __nv_bfloat16 g_Vl[(size_t)NTOK * D_];

// ---------------- warp-level MMA helpers (sm_80 baseline) -------------------
__device__ __forceinline__ void ldsm4(uint32_t* r, uint32_t addr) {
    asm volatile(
        "ldmatrix.sync.aligned.m8n8.x4.shared.b16 {%0,%1,%2,%3}, [%4];"
        : "=r"(r[0]), "=r"(r[1]), "=r"(r[2]), "=r"(r[3]) : "r"(addr));
}
__device__ __forceinline__ void ldsm4t(uint32_t* r, uint32_t addr) {
    asm volatile(
        "ldmatrix.sync.aligned.m8n8.x4.trans.shared.b16 {%0,%1,%2,%3}, [%4];"
        : "=r"(r[0]), "=r"(r[1]), "=r"(r[2]), "=r"(r[3]) : "r"(addr));
}
__device__ __forceinline__ void mma16816(float* c, const uint32_t* a,
                                         const uint32_t* b) {
    asm volatile(
        "mma.sync.aligned.m16n8k16.row.col.f32.bf16.bf16.f32 "
        "{%0,%1,%2,%3}, {%4,%5,%6,%7}, {%8,%9}, {%0,%1,%2,%3};"
        : "+f"(c[0]), "+f"(c[1]), "+f"(c[2]), "+f"(c[3])
        : "r"(a[0]), "r"(a[1]), "r"(a[2]), "r"(a[3]), "r"(b[0]), "r"(b[1]));
}
__device__ __forceinline__ uint32_t smem_u32(const void* p) {
    uint32_t a;
    asm("{ .reg .u64 t; cvta.to.shared.u64 t, %1; cvt.u32.u64 %0, t; }"
        : "=r"(a) : "l"(p));
    return a;
}
__device__ __forceinline__ void split2(float a, float b, uint32_t& hi,
                                       uint32_t& lo) {
    __nv_bfloat16 ha = __float2bfloat16(a), hb = __float2bfloat16(b);
    __nv_bfloat16 la = __float2bfloat16(a - __bfloat162float(ha));
    __nv_bfloat16 lb = __float2bfloat16(b - __bfloat162float(hb));
    __nv_bfloat162 Hh; Hh.x = ha; Hh.y = hb;
    __nv_bfloat162 Ll; Ll.x = la; Ll.y = lb;
    hi = *(uint32_t*)&Hh;
    lo = *(uint32_t*)&Ll;
}

// ---------------- split fp32 -> (hi, lo) bf16 --------------------------------
// ssel: 0=param, 1=g_A, 2=g_Q, 3=g_K, 4=g_V
// dsel: 0=x, 1..4=W, 5=A, 6=Q, 7=K, 8=V
__global__ __launch_bounds__(256) void split_k(const float* src, int ssel,
                                               int dsel, int n4) {
    int i = blockIdx.x * 256 + threadIdx.x;
    if (i >= n4) return;
    const float* s;
    switch (ssel) {
        case 0: s = src; break;
        case 1: s = g_A; break;
        case 2: s = g_Q; break;
        case 3: s = g_K; break;
        default: s = g_V;
    }
    __nv_bfloat16 *hi, *lo;
    switch (dsel) {
        case 0: hi = g_xhi; lo = g_xlo; break;
        case 5: hi = g_Ahi; lo = g_Alo; break;
        case 6: hi = g_Qh;  lo = g_Ql;  break;
        case 7: hi = g_Kh;  lo = g_Kl;  break;
        case 8: hi = g_Vh;  lo = g_Vl;  break;
        default:
            hi = g_Whi + (size_t)(dsel - 1) * 1048576;
            lo = g_Wlo + (size_t)(dsel - 1) * 1048576;
    }
    float4 v = *(const float4*)(s + 4 * (size_t)i);
    float vv[4] = {v.x, v.y, v.z, v.w};
    __nv_bfloat16 h[4], l[4];
#pragma unroll
    for (int j = 0; j < 4; ++j) {
        h[j] = __float2bfloat16(vv[j]);
        l[j] = __float2bfloat16(vv[j] - __bfloat162float(h[j]));
    }
    *(uint2*)(hi + 4 * (size_t)i) = *(uint2*)h;
    *(uint2*)(lo + 4 * (size_t)i) = *(uint2*)l;
}

// ---------------- HMMA split-bf16 GEMM: C = A @ W^T -------------------------
// If wsel<0: use blockIdx.z as weight/output selector (QKV in one launch).
#define GST 40   // smem row stride in bf16

__global__ __launch_bounds__(256) void gemm_mma(int asel, int wsel, int csel,
                                                float* Cout) {
    __shared__ __nv_bfloat16 sAh[128 * GST];
    __shared__ __nv_bfloat16 sAl[128 * GST];
    __shared__ __nv_bfloat16 sWh[128 * GST];
    __shared__ __nv_bfloat16 sWl[128 * GST];

    const int tid = threadIdx.x, wid = tid >> 5, lid = tid & 31;
    const int wr = wid & 1, wc = wid >> 1;
    const int m0 = blockIdx.y * 128, n0 = blockIdx.x * 128;
    const int ws = (wsel < 0) ? (int)blockIdx.z : wsel;
    const int cs = (csel < 0) ? (int)blockIdx.z : csel;

    const __nv_bfloat16* Ah = asel ? g_Ahi : g_xhi;
    const __nv_bfloat16* Al = asel ? g_Alo : g_xlo;
    const __nv_bfloat16* Wh = g_Whi + (size_t)ws * 1048576;
    const __nv_bfloat16* Wl = g_Wlo + (size_t)ws * 1048576;
    float* C;
    switch (cs) {
        case 0: C = g_Q; break;
        case 1: C = g_K; break;
        case 2: C = g_V; break;
        default: C = Cout;
    }

    const uint32_t bAh = smem_u32(sAh), bAl = smem_u32(sAl);
    const uint32_t bWh = smem_u32(sWh), bWl = smem_u32(sWl);

    const int rowSelA = wr * 64 + (lid & 15);
    const int kSelA   = (lid >> 4) * 8;
    const int rowSelW = wc * 32 + ((lid >> 4) * 8) + (lid & 7);
    const int kSelW   = ((lid >> 3) & 1) * 8;

    float acc[4][4][4];
#pragma unroll
    for (int i = 0; i < 4; ++i)
#pragma unroll
        for (int j = 0; j < 4; ++j)
#pragma unroll
            for (int t = 0; t < 4; ++t) acc[i][j][t] = 0.f;

    for (int k0 = 0; k0 < 1024; k0 += 32) {
        __syncthreads();
#pragma unroll
        for (int p = 0; p < 2; ++p) {
            int c = tid + p * 256;
            int row = c >> 2, kc = (c & 3) * 8;
            int so = row * GST + kc;
            size_t ao = (size_t)(m0 + row) * 1024 + k0 + kc;
            size_t wo = (size_t)(n0 + row) * 1024 + k0 + kc;
            *(uint4*)(sAh + so) = *(const uint4*)(Ah + ao);
            *(uint4*)(sAl + so) = *(const uint4*)(Al + ao);
            *(uint4*)(sWh + so) = *(const uint4*)(Wh + wo);
            *(uint4*)(sWl + so) = *(const uint4*)(Wl + wo);
        }
        __syncthreads();

#pragma unroll
        for (int ks = 0; ks < 2; ++ks) {
            uint32_t bh[4][2], bl[4][2];
#pragma unroll
            for (int nt16 = 0; nt16 < 2; ++nt16) {
                uint32_t r[4];
                uint32_t off =
                    (uint32_t)((rowSelW + nt16 * 16) * GST + ks * 16 + kSelW) * 2;
                ldsm4(r, bWh + off);
                bh[nt16 * 2][0] = r[0]; bh[nt16 * 2][1] = r[1];
                bh[nt16 * 2 + 1][0] = r[2]; bh[nt16 * 2 + 1][1] = r[3];
                ldsm4(r, bWl + off);
                bl[nt16 * 2][0] = r[0]; bl[nt16 * 2][1] = r[1];
                bl[nt16 * 2 + 1][0] = r[2]; bl[nt16 * 2 + 1][1] = r[3];
            }
            uint32_t a[4][4];
#pragma unroll
            for (int mt = 0; mt < 4; ++mt)
                ldsm4(a[mt],
                      bAh + (uint32_t)((rowSelA + mt * 16) * GST + ks * 16 + kSelA) * 2);
#pragma unroll
            for (int mt = 0; mt < 4; ++mt)
#pragma unroll
                for (int nt = 0; nt < 4; ++nt) {
                    mma16816(acc[mt][nt], a[mt], bh[nt]);
                    mma16816(acc[mt][nt], a[mt], bl[nt]);
                }
#pragma unroll
            for (int mt = 0; mt < 4; ++mt)
                ldsm4(a[mt],
                      bAl + (uint32_t)((rowSelA + mt * 16) * GST + ks * 16 + kSelA) * 2);
#pragma unroll
            for (int mt = 0; mt < 4; ++mt)
#pragma unroll
                for (int nt = 0; nt < 4; ++nt)
                    mma16816(acc[mt][nt], a[mt], bh[nt]);
        }
    }

    const int g = lid >> 2, j2 = (lid & 3) * 2;
#pragma unroll
    for (int mt = 0; mt < 4; ++mt) {
        int row = m0 + wr * 64 + mt * 16 + g;
#pragma unroll
        for (int nt = 0; nt < 4; ++nt) {
            int col = n0 + wc * 32 + nt * 8 + j2;
            *(float2*)&C[(size_t)row * 1024 + col] =
                make_float2(acc[mt][nt][0], acc[mt][nt][1]);
            *(float2*)&C[(size_t)(row + 8) * 1024 + col] =
                make_float2(acc[mt][nt][2], acc[mt][nt][3]);
        }
    }
}

// ---------------- RoPE trig table -------------------------------------------
__global__ __launch_bounds__(256) void build_trig(const int* __restrict__ pos) {
    int idx = blockIdx.x * blockDim.x + threadIdx.x;
    if (idx >= S_ * 32) return;
    int s = idx >> 5;
    int i = idx & 31;
    double inv = pow(10000.0, -(double)(2 * i) / 64.0);
    double ang = (double)pos[s] * inv;
    g_cos[idx] = (float)cos(ang);
    g_sin[idx] = (float)sin(ang);
}

// ---------------- RoPE apply (in-place; folds 1/8 into Q) -------------------
__global__ __launch_bounds__(256) void rope_apply() {
    int idx = blockIdx.x * blockDim.x + threadIdx.x;
    if (idx >= NTOK * (D_ / 2)) return;
    int i   = idx & 31;
    int r   = idx >> 5;
    int h   = r & 15;
    int tok = r >> 4;
    int s   = tok & (S_ - 1);
    float c  = g_cos[(s << 5) + i];
    float sn = g_sin[(s << 5) + i];
    size_t base = (size_t)tok * D_ + (size_t)h * DK_ + 2 * i;
    float2 q = *(float2*)&g_Q[base];
    *(float2*)&g_Q[base] = make_float2((q.x * c - q.y * sn) * 0.125f,
                                       (q.x * sn + q.y * c) * 0.125f);
    float2 k = *(float2*)&g_K[base];
    *(float2*)&g_K[base] = make_float2(k.x * c - k.y * sn, k.x * sn + k.y * c);
}

// ---------------- fused flash attention (HMMA, split-bf16) ------------------
// grid (16, 64): q-tile of 128 rows (reversed), bh. 8 warps x 16 rows.
// K-tiles of 64 keys. Q scaled by 1/8 already (folded in rope).
#define GSTF 72  // smem row stride (bf16); 144 B -> conflict-free ldmatrix

__global__ __launch_bounds__(256) void flash_mma() {
    __shared__ __nv_bfloat16 sKh[64 * GSTF];
    __shared__ __nv_bfloat16 sKl[64 * GSTF];
    __shared__ __nv_bfloat16 sVh[64 * GSTF];
    __shared__ __nv_bfloat16 sVl[64 * GSTF];

    const int tid = threadIdx.x, wid = tid >> 5, lid = tid & 31;
    const int qt = 15 - (int)blockIdx.x;      // heavy tiles first
    const int bh = blockIdx.y;
    const int b = bh >> 4, h = bh & 15;
    const size_t base = (size_t)b * S_ * D_ + (size_t)h * DK_;
    const int q0 = qt * 128;
    const int g = lid >> 2, j2 = (lid & 3) * 2;
    const int qrow0 = q0 + wid * 16 + g;      // row for c0/c1; +8 for c2/c3

    // Q fragments (A-frag, direct from global; one-time)
    uint32_t qh[4][4], ql[4][4];
#pragma unroll
    for (int ks = 0; ks < 4; ++ks) {
        size_t r0 = base + (size_t)qrow0 * D_ + ks * 16 + j2;
        size_t r1 = base + (size_t)(qrow0 + 8) * D_ + ks * 16 + j2;
        qh[ks][0] = *(const uint32_t*)(g_Qh + r0);
        qh[ks][1] = *(const uint32_t*)(g_Qh + r1);
        qh[ks][2] = *(const uint32_t*)(g_Qh + r0 + 8);
        qh[ks][3] = *(const uint32_t*)(g_Qh + r1 + 8);
        ql[ks][0] = *(const uint32_t*)(g_Ql + r0);
        ql[ks][1] = *(const uint32_t*)(g_Ql + r1);
        ql[ks][2] = *(const uint32_t*)(g_Ql + r0 + 8);
        ql[ks][3] = *(const uint32_t*)(g_Ql + r1 + 8);
    }

    float o[8][4];
#pragma unroll
    for (int nt = 0; nt < 8; ++nt)
#pragma unroll
        for (int t = 0; t < 4; ++t) o[nt][t] = 0.f;
    float m0 = -1e30f, m1 = -1e30f, l0 = 0.f, l1 = 0.f;

    const uint32_t bKh = smem_u32(sKh), bKl = smem_u32(sKl);
    const uint32_t bVh = smem_u32(sVh), bVl = smem_u32(sVl);
    const uint32_t selK =
        (uint32_t)((((lid >> 4) * 8) + (lid & 7)) * GSTF + ((lid >> 3) & 1) * 8) * 2;
    const uint32_t selV =
        (uint32_t)(((((lid >> 3) & 1) * 8) + (lid & 7)) * GSTF + (lid >> 4) * 8) * 2;

    const int nkt = 2 * qt + 2;
    for (int kt = 0; kt < nkt; ++kt) {
        const int k0 = kt * 64;
        __syncthreads();
#pragma unroll
        for (int p = 0; p < 2; ++p) {
            int c = tid + p * 256;
            int row = c >> 3, col8 = (c & 7) * 8;
            size_t go = base + (size_t)(k0 + row) * D_ + col8;
            int so = row * GSTF + col8;
            *(uint4*)(sKh + so) = *(const uint4*)(g_Kh + go);
            *(uint4*)(sKl + so) = *(const uint4*)(g_Kl + go);
            *(uint4*)(sVh + so) = *(const uint4*)(g_Vh + go);
            *(uint4*)(sVl + so) = *(const uint4*)(g_Vl + go);
        }
        __syncthreads();

        // ---- S = Q·K^T (3-product split) ----
        float s[8][4];
#pragma unroll
        for (int nt = 0; nt < 8; ++nt)
#pragma unroll
            for (int t = 0; t < 4; ++t) s[nt][t] = 0.f;

#pragma unroll
        for (int ks = 0; ks < 4; ++ks) {
            uint32_t kbh[8][2], kbl[8][2], r[4];
#pragma unroll
            for (int n16 = 0; n16 < 4; ++n16) {
                uint32_t off = selK + (uint32_t)((n16 * 16) * GSTF + ks * 16) * 2;
                ldsm4(r, bKh + off);
                kbh[2 * n16][0] = r[0]; kbh[2 * n16][1] = r[1];
                kbh[2 * n16 + 1][0] = r[2]; kbh[2 * n16 + 1][1] = r[3];
                ldsm4(r, bKl + off);
                kbl[2 * n16][0] = r[0]; kbl[2 * n16][1] = r[1];
                kbl[2 * n16 + 1][0] = r[2]; kbl[2 * n16 + 1][1] = r[3];
            }
#pragma unroll
            for (int nt = 0; nt < 8; ++nt) {
                mma16816(s[nt], qh[ks], kbh[nt]);
                mma16816(s[nt], ql[ks], kbh[nt]);
                mma16816(s[nt], qh[ks], kbl[nt]);
            }
        }

        // ---- causal mask ----
        if (k0 + 63 > q0 + wid * 16) {
#pragma unroll
            for (int nt = 0; nt < 8; ++nt) {
                int key = k0 + nt * 8 + j2;
                if (key > qrow0)         s[nt][0] = -1e30f;
                if (key + 1 > qrow0)     s[nt][1] = -1e30f;
                if (key > qrow0 + 8)     s[nt][2] = -1e30f;
                if (key + 1 > qrow0 + 8) s[nt][3] = -1e30f;
            }
        }

        // ---- online softmax (rows g and g+8; reduce over quad lanes) ----
        float mx0 = -1e30f, mx1 = -1e30f;
#pragma unroll
        for (int nt = 0; nt < 8; ++nt) {
            mx0 = fmaxf(mx0, fmaxf(s[nt][0], s[nt][1]));
            mx1 = fmaxf(mx1, fmaxf(s[nt][2], s[nt][3]));
        }
        mx0 = fmaxf(mx0, __shfl_xor_sync(0xffffffffu, mx0, 1));
        mx0 = fmaxf(mx0, __shfl_xor_sync(0xffffffffu, mx0, 2));
        mx1 = fmaxf(mx1, __shfl_xor_sync(0xffffffffu, mx1, 1));
        mx1 = fmaxf(mx1, __shfl_xor_sync(0xffffffffu, mx1, 2));
        float mn0 = fmaxf(m0, mx0), mn1 = fmaxf(m1, mx1);
        float a0 = __expf(m0 - mn0), a1 = __expf(m1 - mn1);
        float sum0 = 0.f, sum1 = 0.f;
#pragma unroll
        for (int nt = 0; nt < 8; ++nt) {
            s[nt][0] = __expf(s[nt][0] - mn0);
            s[nt][1] = __expf(s[nt][1] - mn0);
            s[nt][2] = __expf(s[nt][2] - mn1);
            s[nt][3] = __expf(s[nt][3] - mn1);
            sum0 += s[nt][0] + s[nt][1];
            sum1 += s[nt][2] + s[nt][3];
        }
        sum0 += __shfl_xor_sync(0xffffffffu, sum0, 1);
        sum0 += __shfl_xor_sync(0xffffffffu, sum0, 2);
        sum1 += __shfl_xor_sync(0xffffffffu, sum1, 1);
        sum1 += __shfl_xor_sync(0xffffffffu, sum1, 2);
        l0 = l0 * a0 + sum0;
        l1 = l1 * a1 + sum1;
        m0 = mn0; m1 = mn1;
#pragma unroll
        for (int nt = 0; nt < 8; ++nt) {
            o[nt][0] *= a0; o[nt][1] *= a0;
            o[nt][2] *= a1; o[nt][3] *= a1;
        }

        // ---- O += P·V (3-product split; P from registers) ----
#pragma unroll
        for (int ks = 0; ks < 4; ++ks) {
            uint32_t ph[4], pl[4];
            split2(s[2 * ks][0], s[2 * ks][1], ph[0], pl[0]);
            split2(s[2 * ks][2], s[2 * ks][3], ph[1], pl[1]);
            split2(s[2 * ks + 1][0], s[2 * ks + 1][1], ph[2], pl[2]);
            split2(s[2 * ks + 1][2], s[2 * ks + 1][3], ph[3], pl[3]);

            uint32_t vbh[8][2], vbl[8][2], r[4];
#pragma unroll
            for (int n16 = 0; n16 < 4; ++n16) {
                uint32_t off = selV + (uint32_t)((ks * 16) * GSTF + n16 * 16) * 2;
                ldsm4t(r, bVh + off);
                vbh[2 * n16][0] = r[0]; vbh[2 * n16][1] = r[1];
                vbh[2 * n16 + 1][0] = r[2]; vbh[2 * n16 + 1][1] = r[3];
                ldsm4t(r, bVl + off);
                vbl[2 * n16][0] = r[0]; vbl[2 * n16][1] = r[1];
                vbl[2 * n16 + 1][0] = r[2]; vbl[2 * n16 + 1][1] = r[3];
            }
#pragma unroll
            for (int nt = 0; nt < 8; ++nt) {
                mma16816(o[nt], ph, vbh[nt]);
                mma16816(o[nt], pl, vbh[nt]);
                mma16816(o[nt], ph, vbl[nt]);
            }
        }
    }

    // ---- epilogue: normalize, write to g_A (b, s, h, d) ----
    const float i0 = 1.f / l0, i1 = 1.f / l1;
#pragma unroll
    for (int nt = 0; nt < 8; ++nt) {
        size_t r0 = base + (size_t)qrow0 * D_ + nt * 8 + j2;
        size_t r1 = base + (size_t)(qrow0 + 8) * D_ + nt * 8 + j2;
        *(float2*)(g_A + r0) = make_float2(o[nt][0] * i0, o[nt][1] * i0);
        *(float2*)(g_A + r1) = make_float2(o[nt][2] * i1, o[nt][3] * i1);
    }
}

// ---------------- launch -----------------------------------------------------
extern "C" void kernel_launch(void* const* d_in, const int* in_sizes, int n_in,
                              void* d_out, int out_size) {
    int ix = 0, ipos = 1;
    int iw[4] = {2, 3, 4, 5};
    {
        int nw = 0, found_x = 0, found_p = 0, tmp[8];
        for (int i = 0; i < n_in && i < 8; ++i) {
            if (in_sizes[i] == S_) { ipos = i; found_p = 1; }
            else if (in_sizes[i] == NTOK * D_) { ix = i; found_x = 1; }
            else if (nw < 8) tmp[nw++] = i;
        }
        if (found_x && found_p && nw >= 4) {
            iw[0] = tmp[0]; iw[1] = tmp[1]; iw[2] = tmp[2]; iw[3] = tmp[3];
        }
    }

    const float* x  = (const float*)d_in[ix];
    const int* pos  = (const int*)d_in[ipos];
    const float* Wq = (const float*)d_in[iw[0]];
    const float* Wk = (const float*)d_in[iw[1]];
    const float* Wv = (const float*)d_in[iw[2]];
    const float* Wo = (const float*)d_in[iw[3]];
    float* out = (float*)d_out;

    const int nT = NTOK * D_ / 4;   // fp32 elements / 4 per thread
    const int nW = 1048576 / 4;

    split_k<<<(nT + 255) / 256, 256>>>(x, 0, 0, nT);
    split_k<<<(nW + 255) / 256, 256>>>(Wq, 0, 1, nW);
    split_k<<<(nW + 255) / 256, 256>>>(Wk, 0, 2, nW);
    split_k<<<(nW + 255) / 256, 256>>>(Wv, 0, 3, nW);
    split_k<<<(nW + 255) / 256, 256>>>(Wo, 0, 4, nW);

    // QKV projections in ONE launch (blockIdx.z selects weight/output).
    dim3 gqkv(D_ / 128, NTOK / 128, 3);
    gemm_mma<<<gqkv, 256>>>(0, -1, -1, nullptr);

    build_trig<<<(S_ * 32 + 255) / 256, 256>>>(pos);
    rope_apply<<<(NTOK * (D_ / 2) + 255) / 256, 256>>>();

    // bf16 splits of Q, K, V for the flash kernel.
    split_k<<<(nT + 255) / 256, 256>>>(nullptr, 2, 6, nT);
    split_k<<<(nT + 255) / 256, 256>>>(nullptr, 3, 7, nT);
    split_k<<<(nT + 255) / 256, 256>>>(nullptr, 4, 8, nT);

    dim3 fg(S_ / 128, SBH);   // (16, 64)
    flash_mma<<<fg, 256>>>();

    split_k<<<(nT + 255) / 256, 256>>>(nullptr, 1, 5, nT);
    dim3 go(D_ / 128, NTOK / 128, 1);
    gemm_mma<<<go, 256>>>(1, 3, 3, out);
}